// round 1
// baseline (speedup 1.0000x reference)
#include <cuda_runtime.h>
#include <math.h>

// ---------------- problem constants ----------------
#define Lc   12
#define Hc   12
#define Cc   768
#define Vc   50257
#define Bc   4
#define Tc   1024
#define HDc  64
#define Nc   4096        // B*T tokens
#define C3   2304        // 3*C
#define C4   3072        // 4*C

// ---------------- scratch (device globals; no allocs allowed) ----------------
__device__ float g_x  [Nc * Cc];   // residual stream
__device__ float g_h  [Nc * Cc];   // layernorm output / final ln
__device__ float g_qkv[Nc * C3];   // qkv projections
__device__ float g_att[Nc * Cc];   // attention output (heads merged)
__device__ float g_fc [Nc * C4];   // MLP hidden
__device__ float g_nll[Nc];        // per-token nll * mask
__device__ float g_msk[Nc];        // per-token mask

// ---------------- embedding: x = wte[idx] + wpe[t] ----------------
__global__ void k_embed(const int* __restrict__ idx,
                        const float* __restrict__ wte,
                        const float* __restrict__ wpe) {
    int n  = blockIdx.x;
    int id = idx[n];
    int t  = n & (Tc - 1);
    const float* we = wte + (size_t)id * Cc;
    const float* wp = wpe + (size_t)t  * Cc;
    for (int c = threadIdx.x; c < Cc; c += blockDim.x)
        g_x[(size_t)n * Cc + c] = we[c] + wp[c];
}

// ---------------- layernorm: out = (x - mu) * rstd * g + b ----------------
__global__ void k_ln(const float* __restrict__ in, float* __restrict__ out,
                     const float* __restrict__ g, const float* __restrict__ b) {
    int row = blockIdx.x;
    const float* x = in + (size_t)row * Cc;
    float s = 0.f, s2 = 0.f;
    for (int c = threadIdx.x; c < Cc; c += blockDim.x) {
        float v = x[c];
        s += v; s2 += v * v;
    }
    __shared__ float rs[256], rs2[256];
    rs[threadIdx.x] = s; rs2[threadIdx.x] = s2;
    __syncthreads();
    for (int o = 128; o > 0; o >>= 1) {
        if (threadIdx.x < o) { rs[threadIdx.x] += rs[threadIdx.x + o]; rs2[threadIdx.x] += rs2[threadIdx.x + o]; }
        __syncthreads();
    }
    float mu   = rs[0] * (1.0f / Cc);
    float var  = rs2[0] * (1.0f / Cc) - mu * mu;
    float rstd = rsqrtf(var + 1e-5f);
    float* o = out + (size_t)row * Cc;
    for (int c = threadIdx.x; c < Cc; c += blockDim.x)
        o[c] = (x[c] - mu) * rstd * g[c] + b[c];
}

// ---------------- sgemm NN: C = A[M,K] @ B[K,N] (+bias, epilogue) ----------------
// EPI: 0 = bias only, 1 = bias + residual add, 2 = bias + exact GELU
template <int EPI>
__global__ void k_gemm_nn(const float* __restrict__ A, const float* __restrict__ Bm,
                          const float* __restrict__ bias, const float* __restrict__ res,
                          float* __restrict__ Cout, int M, int Nn, int K) {
    const int BM = 128, BN = 128, BK = 8;
    __shared__ float As[BK][BM];
    __shared__ float Bs[BK][BN];
    int tx = threadIdx.x;               // 0..255
    int bm = blockIdx.y * BM, bn = blockIdx.x * BN;
    int tm = tx >> 4, tn = tx & 15;     // 16x16 thread grid, 8x8 each

    float acc[8][8];
#pragma unroll
    for (int i = 0; i < 8; i++)
#pragma unroll
        for (int j = 0; j < 8; j++) acc[i][j] = 0.f;

    int arow = tx >> 1, ak4 = (tx & 1) * 4;   // A: 128 rows x 2 float4
    int bk   = tx >> 5, bn4 = (tx & 31) * 4;  // B: 8 rows x 32 float4

    for (int k0 = 0; k0 < K; k0 += BK) {
        float4 av = *(const float4*)(A + (size_t)(bm + arow) * K + k0 + ak4);
        As[ak4 + 0][arow] = av.x; As[ak4 + 1][arow] = av.y;
        As[ak4 + 2][arow] = av.z; As[ak4 + 3][arow] = av.w;
        float4 bv = *(const float4*)(Bm + (size_t)(k0 + bk) * Nn + bn + bn4);
        *(float4*)&Bs[bk][bn4] = bv;
        __syncthreads();
#pragma unroll
        for (int kk = 0; kk < BK; kk++) {
            float a[8], bb[8];
#pragma unroll
            for (int i = 0; i < 8; i++) a[i]  = As[kk][tm * 8 + i];
#pragma unroll
            for (int j = 0; j < 8; j++) bb[j] = Bs[kk][tn * 8 + j];
#pragma unroll
            for (int i = 0; i < 8; i++)
#pragma unroll
                for (int j = 0; j < 8; j++) acc[i][j] += a[i] * bb[j];
        }
        __syncthreads();
    }

#pragma unroll
    for (int i = 0; i < 8; i++) {
        int r = bm + tm * 8 + i;
#pragma unroll
        for (int j = 0; j < 8; j++) {
            int c = bn + tn * 8 + j;
            float v = acc[i][j] + bias[c];
            if (EPI == 1) v += res[(size_t)r * Nn + c];
            if (EPI == 2) v = 0.5f * v * (1.0f + erff(v * 0.70710678118654752f));
            Cout[(size_t)r * Nn + c] = v;
        }
    }
}

// ---------------- sgemm NT: C = A[M,K] @ Bt[N,K]^T  (logits; N-edge guarded) ----------------
__global__ void k_gemm_nt(const float* __restrict__ A, const float* __restrict__ Bt,
                          float* __restrict__ Cout, int M, int Nn, int K) {
    const int BM = 128, BN = 128, BK = 8;
    __shared__ float As[BK][BM];
    __shared__ float Bs[BK][BN];
    int tx = threadIdx.x;
    int bm = blockIdx.y * BM, bn = blockIdx.x * BN;
    int tm = tx >> 4, tn = tx & 15;

    float acc[8][8];
#pragma unroll
    for (int i = 0; i < 8; i++)
#pragma unroll
        for (int j = 0; j < 8; j++) acc[i][j] = 0.f;

    int arow = tx >> 1, ak4 = (tx & 1) * 4;
    int brow = tx >> 1, bk4 = (tx & 1) * 4;   // 128 n-rows x 2 float4 along K

    for (int k0 = 0; k0 < K; k0 += BK) {
        float4 av = *(const float4*)(A + (size_t)(bm + arow) * K + k0 + ak4);
        As[ak4 + 0][arow] = av.x; As[ak4 + 1][arow] = av.y;
        As[ak4 + 2][arow] = av.z; As[ak4 + 3][arow] = av.w;
        int ng = bn + brow;
        float4 bv = make_float4(0.f, 0.f, 0.f, 0.f);
        if (ng < Nn) bv = *(const float4*)(Bt + (size_t)ng * K + k0 + bk4);
        Bs[bk4 + 0][brow] = bv.x; Bs[bk4 + 1][brow] = bv.y;
        Bs[bk4 + 2][brow] = bv.z; Bs[bk4 + 3][brow] = bv.w;
        __syncthreads();
#pragma unroll
        for (int kk = 0; kk < BK; kk++) {
            float a[8], bb[8];
#pragma unroll
            for (int i = 0; i < 8; i++) a[i]  = As[kk][tm * 8 + i];
#pragma unroll
            for (int j = 0; j < 8; j++) bb[j] = Bs[kk][tn * 8 + j];
#pragma unroll
            for (int i = 0; i < 8; i++)
#pragma unroll
                for (int j = 0; j < 8; j++) acc[i][j] += a[i] * bb[j];
        }
        __syncthreads();
    }

#pragma unroll
    for (int i = 0; i < 8; i++) {
        int r = bm + tm * 8 + i;
#pragma unroll
        for (int j = 0; j < 8; j++) {
            int c = bn + tn * 8 + j;
            if (c < Nn) Cout[(size_t)r * Nn + c] = acc[i][j];
        }
    }
}

// ---------------- flash attention (fp32, no mask), Br=Bc=64 ----------------
// grid: (T/64, H, B), 256 threads. qkv layout: [n, 3C], q|k|v at offsets 0|C|2C,
// head h occupies columns h*64..h*64+63. Output written to g_att [n, C].
#define ATTN_SMEM (4 * 64 * 65 * 4 + 3 * 64 * 4)
__global__ void k_attn(const float* __restrict__ qkv) {
    extern __shared__ float sm[];
    float* Qs  = sm;                 // 64 x 65
    float* Ks  = Qs + 64 * 65;       // 64 x 65
    float* Vs  = Ks + 64 * 65;       // 64 x 65
    float* Ss  = Vs + 64 * 65;       // 64 x 65
    float* m_s = Ss + 64 * 65;       // 64
    float* l_s = m_s + 64;           // 64
    float* f_s = l_s + 64;           // 64

    int tx = threadIdx.x;
    int qt0 = blockIdx.x * 64;
    int h   = blockIdx.y;
    int b   = blockIdx.z;
    const float scale = 0.125f;      // 1/sqrt(64)

    // load Q tile (scaled)
#pragma unroll
    for (int it = 0; it < 4; it++) {
        int id = it * 256 + tx;
        int row = id >> 4, q4 = (id & 15) * 4;
        float4 v = *(const float4*)(qkv + (size_t)(b * Tc + qt0 + row) * C3 + h * HDc + q4);
        Qs[row * 65 + q4 + 0] = v.x * scale;
        Qs[row * 65 + q4 + 1] = v.y * scale;
        Qs[row * 65 + q4 + 2] = v.z * scale;
        Qs[row * 65 + q4 + 3] = v.w * scale;
    }
    if (tx < 64) { m_s[tx] = -3.0e38f; l_s[tx] = 0.f; }

    int r0 = (tx >> 4) * 4, c0 = (tx & 15) * 4;
    float o[4][4];
#pragma unroll
    for (int i = 0; i < 4; i++)
#pragma unroll
        for (int j = 0; j < 4; j++) o[i][j] = 0.f;

    for (int kt = 0; kt < Tc / 64; kt++) {
        int kt0 = kt * 64;
        // load K, V tiles
#pragma unroll
        for (int it = 0; it < 4; it++) {
            int id = it * 256 + tx;
            int row = id >> 4, q4 = (id & 15) * 4;
            size_t base = (size_t)(b * Tc + kt0 + row) * C3 + h * HDc + q4;
            float4 kv = *(const float4*)(qkv + base + Cc);
            Ks[row * 65 + q4 + 0] = kv.x; Ks[row * 65 + q4 + 1] = kv.y;
            Ks[row * 65 + q4 + 2] = kv.z; Ks[row * 65 + q4 + 3] = kv.w;
            float4 vv = *(const float4*)(qkv + base + 2 * Cc);
            Vs[row * 65 + q4 + 0] = vv.x; Vs[row * 65 + q4 + 1] = vv.y;
            Vs[row * 65 + q4 + 2] = vv.z; Vs[row * 65 + q4 + 3] = vv.w;
        }
        __syncthreads();

        // S = Qs @ Ks^T  (each thread 4x4)
        float acc[4][4];
#pragma unroll
        for (int i = 0; i < 4; i++)
#pragma unroll
            for (int j = 0; j < 4; j++) acc[i][j] = 0.f;
#pragma unroll 8
        for (int d = 0; d < 64; d++) {
            float a0 = Qs[(r0 + 0) * 65 + d], a1 = Qs[(r0 + 1) * 65 + d];
            float a2 = Qs[(r0 + 2) * 65 + d], a3 = Qs[(r0 + 3) * 65 + d];
            float b0 = Ks[(c0 + 0) * 65 + d], b1 = Ks[(c0 + 1) * 65 + d];
            float b2 = Ks[(c0 + 2) * 65 + d], b3 = Ks[(c0 + 3) * 65 + d];
            acc[0][0] += a0 * b0; acc[0][1] += a0 * b1; acc[0][2] += a0 * b2; acc[0][3] += a0 * b3;
            acc[1][0] += a1 * b0; acc[1][1] += a1 * b1; acc[1][2] += a1 * b2; acc[1][3] += a1 * b3;
            acc[2][0] += a2 * b0; acc[2][1] += a2 * b1; acc[2][2] += a2 * b2; acc[2][3] += a2 * b3;
            acc[3][0] += a3 * b0; acc[3][1] += a3 * b1; acc[3][2] += a3 * b2; acc[3][3] += a3 * b3;
        }
#pragma unroll
        for (int i = 0; i < 4; i++)
#pragma unroll
            for (int j = 0; j < 4; j++) Ss[(r0 + i) * 65 + c0 + j] = acc[i][j];
        __syncthreads();

        // online softmax row update (one thread per row)
        if (tx < 64) {
            float mold = m_s[tx];
            float mx = mold;
            for (int j = 0; j < 64; j++) mx = fmaxf(mx, Ss[tx * 65 + j]);
            float f = expf(mold - mx);
            float s = 0.f;
            for (int j = 0; j < 64; j++) {
                float p = expf(Ss[tx * 65 + j] - mx);
                Ss[tx * 65 + j] = p;
                s += p;
            }
            l_s[tx] = l_s[tx] * f + s;
            m_s[tx] = mx;
            f_s[tx] = f;
        }
        __syncthreads();

        // rescale O and accumulate P @ V
#pragma unroll
        for (int i = 0; i < 4; i++) {
            float f = f_s[r0 + i];
#pragma unroll
            for (int j = 0; j < 4; j++) o[i][j] *= f;
        }
#pragma unroll 8
        for (int kc = 0; kc < 64; kc++) {
            float p0 = Ss[(r0 + 0) * 65 + kc], p1 = Ss[(r0 + 1) * 65 + kc];
            float p2 = Ss[(r0 + 2) * 65 + kc], p3 = Ss[(r0 + 3) * 65 + kc];
            float v0 = Vs[kc * 65 + c0 + 0], v1 = Vs[kc * 65 + c0 + 1];
            float v2 = Vs[kc * 65 + c0 + 2], v3 = Vs[kc * 65 + c0 + 3];
            o[0][0] += p0 * v0; o[0][1] += p0 * v1; o[0][2] += p0 * v2; o[0][3] += p0 * v3;
            o[1][0] += p1 * v0; o[1][1] += p1 * v1; o[1][2] += p1 * v2; o[1][3] += p1 * v3;
            o[2][0] += p2 * v0; o[2][1] += p2 * v1; o[2][2] += p2 * v2; o[2][3] += p2 * v3;
            o[3][0] += p3 * v0; o[3][1] += p3 * v1; o[3][2] += p3 * v2; o[3][3] += p3 * v3;
        }
        __syncthreads();   // protect Ks/Vs before next tile load
    }

#pragma unroll
    for (int i = 0; i < 4; i++) {
        float inv = 1.0f / l_s[r0 + i];
        size_t base = (size_t)(b * Tc + qt0 + r0 + i) * Cc + h * HDc + c0;
#pragma unroll
        for (int j = 0; j < 4; j++) g_att[base + j] = o[i][j] * inv;
    }
}

// ---------------- per-row NLL (online logsumexp over V) ----------------
__global__ void k_nll(const float* __restrict__ logits, const int* __restrict__ targets) {
    int row = blockIdx.x;
    int tid = threadIdx.x;
    const float* lr = logits + (size_t)row * Vc;
    float m = -3.0e38f, s = 0.f;
    for (int j = tid; j < Vc; j += 256) {
        float v = lr[j];
        if (v > m) { s = s * expf(m - v) + 1.0f; m = v; }
        else       { s += expf(v - m); }
    }
    __shared__ float sm_[256], ss_[256];
    sm_[tid] = m; ss_[tid] = s;
    __syncthreads();
    for (int o = 128; o > 0; o >>= 1) {
        if (tid < o) {
            float m1 = sm_[tid], s1 = ss_[tid];
            float m2 = sm_[tid + o], s2 = ss_[tid + o];
            float M = fmaxf(m1, m2);
            sm_[tid] = M;
            ss_[tid] = s1 * expf(m1 - M) + s2 * expf(m2 - M);
        }
        __syncthreads();
    }
    if (tid == 0) {
        float lse = sm_[0] + logf(ss_[0]);
        int tg = targets[row];
        float msk = (tg != 0) ? 1.0f : 0.0f;
        g_nll[row] = (lse - lr[tg]) * msk;
        g_msk[row] = msk;
    }
}

// ---------------- deterministic loss reduce ----------------
__global__ void k_loss_reduce(float* __restrict__ out_loss) {
    __shared__ float sn[1024], sd[1024];
    int tid = threadIdx.x;
    float n = 0.f, d = 0.f;
    for (int i = tid; i < Nc; i += 1024) { n += g_nll[i]; d += g_msk[i]; }
    sn[tid] = n; sd[tid] = d;
    __syncthreads();
    for (int o = 512; o > 0; o >>= 1) {
        if (tid < o) { sn[tid] += sn[tid + o]; sd[tid] += sd[tid + o]; }
        __syncthreads();
    }
    if (tid == 0) *out_loss = sn[0] / fmaxf(sd[0], 1.0f);
}

// ---------------- launch ----------------
extern "C" void kernel_launch(void* const* d_in, const int* in_sizes, int n_in,
                              void* d_out, int out_size) {
    const int*   idx    = (const int*)  d_in[0];
    const int*   tgt    = (const int*)  d_in[1];
    const float* wte    = (const float*)d_in[2];
    const float* wpe    = (const float*)d_in[3];
    const float* ln1_g  = (const float*)d_in[4];
    const float* ln1_b  = (const float*)d_in[5];
    const float* w_qkv  = (const float*)d_in[6];
    const float* b_qkv  = (const float*)d_in[7];
    const float* w_proj = (const float*)d_in[8];
    const float* b_proj = (const float*)d_in[9];
    const float* ln2_g  = (const float*)d_in[10];
    const float* ln2_b  = (const float*)d_in[11];
    const float* w_fc   = (const float*)d_in[12];
    const float* b_fc   = (const float*)d_in[13];
    const float* w_fc2  = (const float*)d_in[14];
    const float* b_fc2  = (const float*)d_in[15];
    const float* lnf_g  = (const float*)d_in[16];
    const float* lnf_b  = (const float*)d_in[17];
    const float* lm_w   = (const float*)d_in[18];
    float* out = (float*)d_out;

    float *px, *ph, *pqkv, *patt, *pfc;
    cudaGetSymbolAddress((void**)&px,   g_x);
    cudaGetSymbolAddress((void**)&ph,   g_h);
    cudaGetSymbolAddress((void**)&pqkv, g_qkv);
    cudaGetSymbolAddress((void**)&patt, g_att);
    cudaGetSymbolAddress((void**)&pfc,  g_fc);

    cudaFuncSetAttribute(k_attn, cudaFuncAttributeMaxDynamicSharedMemorySize, ATTN_SMEM);

    // embedding
    k_embed<<<Nc, 256>>>(idx, wte, wpe);

    for (int l = 0; l < Lc; l++) {
        const float* g1 = ln1_g + (size_t)l * Cc;
        const float* b1 = ln1_b + (size_t)l * Cc;
        const float* wq = w_qkv + (size_t)l * Cc * C3;
        const float* bq = b_qkv + (size_t)l * C3;
        const float* wp = w_proj + (size_t)l * Cc * Cc;
        const float* bp = b_proj + (size_t)l * Cc;
        const float* g2 = ln2_g + (size_t)l * Cc;
        const float* b2 = ln2_b + (size_t)l * Cc;
        const float* wf = w_fc + (size_t)l * Cc * C4;
        const float* bf = b_fc + (size_t)l * C4;
        const float* w2 = w_fc2 + (size_t)l * C4 * Cc;
        const float* bz = b_fc2 + (size_t)l * Cc;

        // ln1
        k_ln<<<Nc, 256>>>(px, ph, g1, b1);
        // qkv = h @ Wq + bq    [4096,768]x[768,2304]
        k_gemm_nn<0><<<dim3(C3 / 128, Nc / 128), 256>>>(ph, wq, bq, nullptr, pqkv, Nc, C3, Cc);
        // attention
        k_attn<<<dim3(Tc / 64, Hc, Bc), 256, ATTN_SMEM>>>(pqkv);
        // x = x + att @ Wp + bp
        k_gemm_nn<1><<<dim3(Cc / 128, Nc / 128), 256>>>(patt, wp, bp, px, px, Nc, Cc, Cc);
        // ln2
        k_ln<<<Nc, 256>>>(px, ph, g2, b2);
        // fc = gelu(h @ Wf + bf)
        k_gemm_nn<2><<<dim3(C4 / 128, Nc / 128), 256>>>(ph, wf, bf, nullptr, pfc, Nc, C4, Cc);
        // x = x + fc @ W2 + b2
        k_gemm_nn<1><<<dim3(Cc / 128, Nc / 128), 256>>>(pfc, w2, bz, px, px, Nc, Cc, C4);
    }

    // final layernorm
    k_ln<<<Nc, 256>>>(px, ph, lnf_g, lnf_b);

    const long long NV = (long long)Nc * Vc;
    if ((long long)out_size >= NV) {
        // logits = h @ lm_w^T  -> d_out
        k_gemm_nt<<<dim3((Vc + 127) / 128, Nc / 128), 256>>>(ph, lm_w, out, Nc, Vc, Cc);
        // loss
        k_nll<<<Nc, 256>>>(out, tgt);
        if ((long long)out_size >= NV + 1)
            k_loss_reduce<<<1, 1024>>>(out + NV);
    }
}

// round 2
// speedup vs baseline: 2.0772x; 2.0772x over previous
#include <cuda_runtime.h>
#include <math.h>

// ---------------- problem constants ----------------
#define Lc   12
#define Hc   12
#define Cc   768
#define Vc   50257
#define Bc   4
#define Tc   1024
#define HDc  64
#define Nc   4096        // B*T tokens
#define C3   2304        // 3*C
#define C4   3072        // 4*C

// ---------------- scratch (device globals; no allocs allowed) ----------------
__device__ float g_x  [Nc * Cc];
__device__ float g_h  [Nc * Cc];
__device__ float g_qkv[Nc * C3];
__device__ float g_att[Nc * Cc];
__device__ float g_fc [Nc * C4];
__device__ float g_nll[Nc];
__device__ float g_msk[Nc];

// ---------------- small helpers ----------------
__device__ __forceinline__ unsigned f2tf32(float x) {
    unsigned r;
    asm("cvt.rna.tf32.f32 %0, %1;" : "=r"(r) : "f"(x));
    return r;
}
__device__ __forceinline__ void mma_tf32(float* c, const unsigned* a, const unsigned* b) {
    asm volatile(
        "mma.sync.aligned.m16n8k8.row.col.f32.tf32.tf32.f32 "
        "{%0,%1,%2,%3}, {%4,%5,%6,%7}, {%8,%9}, {%0,%1,%2,%3};"
        : "+f"(c[0]), "+f"(c[1]), "+f"(c[2]), "+f"(c[3])
        : "r"(a[0]), "r"(a[1]), "r"(a[2]), "r"(a[3]), "r"(b[0]), "r"(b[1]));
}
__device__ __forceinline__ void cpa16(void* s, const void* g) {
    unsigned sa = (unsigned)__cvta_generic_to_shared(s);
    asm volatile("cp.async.cg.shared.global [%0], [%1], 16;" :: "r"(sa), "l"(g));
}
__device__ __forceinline__ void cpa_commit() { asm volatile("cp.async.commit_group;"); }
__device__ __forceinline__ void cpa_wait0()  { asm volatile("cp.async.wait_group 0;"); }

// ---------------- embedding ----------------
__global__ void k_embed(const int* __restrict__ idx,
                        const float* __restrict__ wte,
                        const float* __restrict__ wpe) {
    int n  = blockIdx.x;
    int id = idx[n];
    int t  = n & (Tc - 1);
    const float* we = wte + (size_t)id * Cc;
    const float* wp = wpe + (size_t)t  * Cc;
    for (int c = threadIdx.x; c < Cc; c += blockDim.x)
        g_x[(size_t)n * Cc + c] = we[c] + wp[c];
}

// ---------------- layernorm ----------------
__global__ void k_ln(const float* __restrict__ in, float* __restrict__ out,
                     const float* __restrict__ g, const float* __restrict__ b) {
    int row = blockIdx.x;
    const float* x = in + (size_t)row * Cc;
    float s = 0.f, s2 = 0.f;
    for (int c = threadIdx.x; c < Cc; c += blockDim.x) {
        float v = x[c];
        s += v; s2 += v * v;
    }
    __shared__ float rs[256], rs2[256];
    rs[threadIdx.x] = s; rs2[threadIdx.x] = s2;
    __syncthreads();
    for (int o = 128; o > 0; o >>= 1) {
        if (threadIdx.x < o) { rs[threadIdx.x] += rs[threadIdx.x + o]; rs2[threadIdx.x] += rs2[threadIdx.x + o]; }
        __syncthreads();
    }
    float mu   = rs[0] * (1.0f / Cc);
    float var  = rs2[0] * (1.0f / Cc) - mu * mu;
    float rstd = rsqrtf(var + 1e-5f);
    float* o = out + (size_t)row * Cc;
    for (int c = threadIdx.x; c < Cc; c += blockDim.x)
        o[c] = (x[c] - mu) * rstd * g[c] + b[c];
}

// ---------------- tf32 tensor-core GEMM ----------------
// BLAY: 0 -> B is [K,N] (NN);  1 -> B is [N,K] (NT, N edge guarded)
// EPI:  0 bias, 1 bias+residual, 2 bias+exact GELU, 3 none (logits)
// Tiles: BM=128, BN=128, BK=32; 256 threads (8 warps, 4 x 2); warp tile 32x64.
template <int BLAY, int EPI>
__global__ void __launch_bounds__(256)
k_gemm_t(const float* __restrict__ A, const float* __restrict__ Bm,
         const float* __restrict__ bias, const float* __restrict__ res,
         float* __restrict__ Cout, int M, int Nn, int K) {
    extern __shared__ float smem[];
    const int ASZ = 128 * 36;                         // A stage: [128][36]
    const int BSZ = (BLAY == 0) ? 32 * 132 : 128 * 36; // B stage
    float* As[2] = { smem,            smem + ASZ };
    float* Bs[2] = { smem + 2 * ASZ,  smem + 2 * ASZ + BSZ };

    int tx = threadIdx.x;
    int lane = tx & 31, wid = tx >> 5;
    int warp_m = wid & 3, warp_n = wid >> 2;          // 4 x 2 warp grid
    int bm = blockIdx.y * 128, bn = blockIdx.x * 128;

    float acc[2][8][4];
#pragma unroll
    for (int i = 0; i < 2; i++)
#pragma unroll
        for (int j = 0; j < 8; j++)
#pragma unroll
            for (int k = 0; k < 4; k++) acc[i][j][k] = 0.f;

    const int KT = K / 32;

    // ---- tile loaders (cp.async) ----
    auto load_tile = [&](int st, int k0) {
        // A: 128 rows x 32 cols
#pragma unroll
        for (int it = 0; it < 4; it++) {
            int r = (tx >> 3) + it * 32;
            int c = (tx & 7) * 4;
            cpa16(&As[st][r * 36 + c], A + (size_t)(bm + r) * K + k0 + c);
        }
        if (BLAY == 0) {
            // B: 32 k-rows x 128 n-cols (shapes always divide 128)
#pragma unroll
            for (int it = 0; it < 4; it++) {
                int r = (tx >> 5) + it * 8;
                int c = (tx & 31) * 4;
                cpa16(&Bs[st][r * 132 + c], Bm + (size_t)(k0 + r) * Nn + bn + c);
            }
        } else {
            // B: 128 n-rows x 32 k-cols, guard n edge
#pragma unroll
            for (int it = 0; it < 4; it++) {
                int r = (tx >> 3) + it * 32;
                int c = (tx & 7) * 4;
                int n = bn + r;
                if (n < Nn) {
                    cpa16(&Bs[st][r * 36 + c], Bm + (size_t)n * K + k0 + c);
                } else {
                    *(float4*)&Bs[st][r * 36 + c] = make_float4(0.f, 0.f, 0.f, 0.f);
                }
            }
        }
        cpa_commit();
    };

    load_tile(0, 0);

    for (int kt = 0; kt < KT; kt++) {
        cpa_wait0();
        __syncthreads();
        if (kt + 1 < KT) load_tile((kt + 1) & 1, (kt + 1) * 32);

        const float* A_s = As[kt & 1];
        const float* B_s = Bs[kt & 1];
        int lr = lane >> 2, lc = lane & 3;

#pragma unroll
        for (int ks = 0; ks < 32; ks += 8) {
            unsigned af[2][4];
#pragma unroll
            for (int mt = 0; mt < 2; mt++) {
                int r = warp_m * 32 + mt * 16 + lr;
                int c = ks + lc;
                af[mt][0] = f2tf32(A_s[r * 36 + c]);
                af[mt][1] = f2tf32(A_s[(r + 8) * 36 + c]);
                af[mt][2] = f2tf32(A_s[r * 36 + c + 4]);
                af[mt][3] = f2tf32(A_s[(r + 8) * 36 + c + 4]);
            }
            unsigned bf[8][2];
#pragma unroll
            for (int nt = 0; nt < 8; nt++) {
                int n = warp_n * 64 + nt * 8 + lr;
                int kk = ks + lc;
                if (BLAY == 0) {
                    bf[nt][0] = f2tf32(B_s[kk * 132 + n]);
                    bf[nt][1] = f2tf32(B_s[(kk + 4) * 132 + n]);
                } else {
                    bf[nt][0] = f2tf32(B_s[n * 36 + kk]);
                    bf[nt][1] = f2tf32(B_s[n * 36 + kk + 4]);
                }
            }
#pragma unroll
            for (int mt = 0; mt < 2; mt++)
#pragma unroll
                for (int nt = 0; nt < 8; nt++)
                    mma_tf32(acc[mt][nt], af[mt], bf[nt]);
        }
        __syncthreads();
    }

    // ---- epilogue ----
    int lr = lane >> 2, lc = lane & 3;
#pragma unroll
    for (int mt = 0; mt < 2; mt++) {
#pragma unroll
        for (int nt = 0; nt < 8; nt++) {
            int c0 = bn + warp_n * 64 + nt * 8 + lc * 2;
#pragma unroll
            for (int h = 0; h < 2; h++) {
                int r = bm + warp_m * 32 + mt * 16 + lr + h * 8;
                float v0 = acc[mt][nt][h * 2 + 0];
                float v1 = acc[mt][nt][h * 2 + 1];
                if (EPI != 3) { v0 += bias[c0]; v1 += bias[c0 + 1]; }
                if (EPI == 1) {
                    v0 += res[(size_t)r * Nn + c0];
                    v1 += res[(size_t)r * Nn + c0 + 1];
                }
                if (EPI == 2) {
                    v0 = 0.5f * v0 * (1.0f + erff(v0 * 0.70710678118654752f));
                    v1 = 0.5f * v1 * (1.0f + erff(v1 * 0.70710678118654752f));
                }
                if (BLAY == 1) {
                    if (c0     < Nn) Cout[(size_t)r * Nn + c0]     = v0;
                    if (c0 + 1 < Nn) Cout[(size_t)r * Nn + c0 + 1] = v1;
                } else {
                    *(float2*)&Cout[(size_t)r * Nn + c0] = make_float2(v0, v1);
                }
            }
        }
    }
}

// ---------------- flash attention (fp32), Br=Bc=64, parallel softmax ----------------
#define ATTN_SMEM (4 * 64 * 65 * 4 + 3 * 64 * 4)
__global__ void k_attn(const float* __restrict__ qkv) {
    extern __shared__ float sm[];
    float* Qs  = sm;                 // 64 x 65
    float* Ks  = Qs + 64 * 65;
    float* Vs  = Ks + 64 * 65;
    float* Ss  = Vs + 64 * 65;
    float* m_s = Ss + 64 * 65;       // 64
    float* l_s = m_s + 64;
    float* f_s = l_s + 64;

    int tx = threadIdx.x;
    int qt0 = blockIdx.x * 64;
    int h   = blockIdx.y;
    int b   = blockIdx.z;
    const float scale = 0.125f;

#pragma unroll
    for (int it = 0; it < 4; it++) {
        int id = it * 256 + tx;
        int row = id >> 4, q4 = (id & 15) * 4;
        float4 v = *(const float4*)(qkv + (size_t)(b * Tc + qt0 + row) * C3 + h * HDc + q4);
        Qs[row * 65 + q4 + 0] = v.x * scale;
        Qs[row * 65 + q4 + 1] = v.y * scale;
        Qs[row * 65 + q4 + 2] = v.z * scale;
        Qs[row * 65 + q4 + 3] = v.w * scale;
    }
    if (tx < 64) { m_s[tx] = -3.0e38f; l_s[tx] = 0.f; }

    int r0 = (tx >> 4) * 4, c0 = (tx & 15) * 4;
    float o[4][4];
#pragma unroll
    for (int i = 0; i < 4; i++)
#pragma unroll
        for (int j = 0; j < 4; j++) o[i][j] = 0.f;

    for (int kt = 0; kt < Tc / 64; kt++) {
        int kt0 = kt * 64;
#pragma unroll
        for (int it = 0; it < 4; it++) {
            int id = it * 256 + tx;
            int row = id >> 4, q4 = (id & 15) * 4;
            size_t base = (size_t)(b * Tc + kt0 + row) * C3 + h * HDc + q4;
            float4 kv = *(const float4*)(qkv + base + Cc);
            Ks[row * 65 + q4 + 0] = kv.x; Ks[row * 65 + q4 + 1] = kv.y;
            Ks[row * 65 + q4 + 2] = kv.z; Ks[row * 65 + q4 + 3] = kv.w;
            float4 vv = *(const float4*)(qkv + base + 2 * Cc);
            Vs[row * 65 + q4 + 0] = vv.x; Vs[row * 65 + q4 + 1] = vv.y;
            Vs[row * 65 + q4 + 2] = vv.z; Vs[row * 65 + q4 + 3] = vv.w;
        }
        __syncthreads();

        float acc[4][4];
#pragma unroll
        for (int i = 0; i < 4; i++)
#pragma unroll
            for (int j = 0; j < 4; j++) acc[i][j] = 0.f;
#pragma unroll 8
        for (int d = 0; d < 64; d++) {
            float a0 = Qs[(r0 + 0) * 65 + d], a1 = Qs[(r0 + 1) * 65 + d];
            float a2 = Qs[(r0 + 2) * 65 + d], a3 = Qs[(r0 + 3) * 65 + d];
            float b0 = Ks[(c0 + 0) * 65 + d], b1 = Ks[(c0 + 1) * 65 + d];
            float b2 = Ks[(c0 + 2) * 65 + d], b3 = Ks[(c0 + 3) * 65 + d];
            acc[0][0] += a0 * b0; acc[0][1] += a0 * b1; acc[0][2] += a0 * b2; acc[0][3] += a0 * b3;
            acc[1][0] += a1 * b0; acc[1][1] += a1 * b1; acc[1][2] += a1 * b2; acc[1][3] += a1 * b3;
            acc[2][0] += a2 * b0; acc[2][1] += a2 * b1; acc[2][2] += a2 * b2; acc[2][3] += a2 * b3;
            acc[3][0] += a3 * b0; acc[3][1] += a3 * b1; acc[3][2] += a3 * b2; acc[3][3] += a3 * b3;
        }
#pragma unroll
        for (int i = 0; i < 4; i++)
#pragma unroll
            for (int j = 0; j < 4; j++) Ss[(r0 + i) * 65 + c0 + j] = acc[i][j];
        __syncthreads();

        // parallel online softmax: 4 threads per row, shuffle reduce
        {
            int row = tx >> 2, q = tx & 3;
            float* srow = &Ss[row * 65];
            float mold = m_s[row];                      // read before any lane writes
            float mloc = -3.0e38f;
#pragma unroll
            for (int j = q * 16; j < q * 16 + 16; j++) mloc = fmaxf(mloc, srow[j]);
            mloc = fmaxf(mloc, __shfl_xor_sync(0xffffffffu, mloc, 1));
            mloc = fmaxf(mloc, __shfl_xor_sync(0xffffffffu, mloc, 2));
            float mx = fmaxf(mold, mloc);
            float s = 0.f;
#pragma unroll
            for (int j = q * 16; j < q * 16 + 16; j++) {
                float p = expf(srow[j] - mx);
                srow[j] = p;
                s += p;
            }
            s += __shfl_xor_sync(0xffffffffu, s, 1);
            s += __shfl_xor_sync(0xffffffffu, s, 2);
            if (q == 0) {
                float f = expf(mold - mx);
                l_s[row] = l_s[row] * f + s;
                m_s[row] = mx;
                f_s[row] = f;
            }
        }
        __syncthreads();

#pragma unroll
        for (int i = 0; i < 4; i++) {
            float f = f_s[r0 + i];
#pragma unroll
            for (int j = 0; j < 4; j++) o[i][j] *= f;
        }
#pragma unroll 8
        for (int kc = 0; kc < 64; kc++) {
            float p0 = Ss[(r0 + 0) * 65 + kc], p1 = Ss[(r0 + 1) * 65 + kc];
            float p2 = Ss[(r0 + 2) * 65 + kc], p3 = Ss[(r0 + 3) * 65 + kc];
            float v0 = Vs[kc * 65 + c0 + 0], v1 = Vs[kc * 65 + c0 + 1];
            float v2 = Vs[kc * 65 + c0 + 2], v3 = Vs[kc * 65 + c0 + 3];
            o[0][0] += p0 * v0; o[0][1] += p0 * v1; o[0][2] += p0 * v2; o[0][3] += p0 * v3;
            o[1][0] += p1 * v0; o[1][1] += p1 * v1; o[1][2] += p1 * v2; o[1][3] += p1 * v3;
            o[2][0] += p2 * v0; o[2][1] += p2 * v1; o[2][2] += p2 * v2; o[2][3] += p2 * v3;
            o[3][0] += p3 * v0; o[3][1] += p3 * v1; o[3][2] += p3 * v2; o[3][3] += p3 * v3;
        }
        __syncthreads();
    }

#pragma unroll
    for (int i = 0; i < 4; i++) {
        float inv = 1.0f / l_s[r0 + i];
        size_t base = (size_t)(b * Tc + qt0 + r0 + i) * Cc + h * HDc + c0;
#pragma unroll
        for (int j = 0; j < 4; j++) g_att[base + j] = o[i][j] * inv;
    }
}

// ---------------- per-row NLL ----------------
__global__ void k_nll(const float* __restrict__ logits, const int* __restrict__ targets) {
    int row = blockIdx.x;
    int tid = threadIdx.x;
    const float* lr = logits + (size_t)row * Vc;
    float m = -3.0e38f, s = 0.f;
    for (int j = tid; j < Vc; j += 256) {
        float v = lr[j];
        if (v > m) { s = s * expf(m - v) + 1.0f; m = v; }
        else       { s += expf(v - m); }
    }
    __shared__ float sm_[256], ss_[256];
    sm_[tid] = m; ss_[tid] = s;
    __syncthreads();
    for (int o = 128; o > 0; o >>= 1) {
        if (tid < o) {
            float m1 = sm_[tid], s1 = ss_[tid];
            float m2 = sm_[tid + o], s2 = ss_[tid + o];
            float M = fmaxf(m1, m2);
            sm_[tid] = M;
            ss_[tid] = s1 * expf(m1 - M) + s2 * expf(m2 - M);
        }
        __syncthreads();
    }
    if (tid == 0) {
        float lse = sm_[0] + logf(ss_[0]);
        int tg = targets[row];
        float msk = (tg != 0) ? 1.0f : 0.0f;
        g_nll[row] = (lse - lr[tg]) * msk;
        g_msk[row] = msk;
    }
}

// ---------------- deterministic loss reduce ----------------
__global__ void k_loss_reduce(float* __restrict__ out_loss) {
    __shared__ float sn[1024], sd[1024];
    int tid = threadIdx.x;
    float n = 0.f, d = 0.f;
    for (int i = tid; i < Nc; i += 1024) { n += g_nll[i]; d += g_msk[i]; }
    sn[tid] = n; sd[tid] = d;
    __syncthreads();
    for (int o = 512; o > 0; o >>= 1) {
        if (tid < o) { sn[tid] += sn[tid + o]; sd[tid] += sd[tid + o]; }
        __syncthreads();
    }
    if (tid == 0) *out_loss = sn[0] / fmaxf(sd[0], 1.0f);
}

// ---------------- launch ----------------
extern "C" void kernel_launch(void* const* d_in, const int* in_sizes, int n_in,
                              void* d_out, int out_size) {
    const int*   idx    = (const int*)  d_in[0];
    const int*   tgt    = (const int*)  d_in[1];
    const float* wte    = (const float*)d_in[2];
    const float* wpe    = (const float*)d_in[3];
    const float* ln1_g  = (const float*)d_in[4];
    const float* ln1_b  = (const float*)d_in[5];
    const float* w_qkv  = (const float*)d_in[6];
    const float* b_qkv  = (const float*)d_in[7];
    const float* w_proj = (const float*)d_in[8];
    const float* b_proj = (const float*)d_in[9];
    const float* ln2_g  = (const float*)d_in[10];
    const float* ln2_b  = (const float*)d_in[11];
    const float* w_fc   = (const float*)d_in[12];
    const float* b_fc   = (const float*)d_in[13];
    const float* w_fc2  = (const float*)d_in[14];
    const float* b_fc2  = (const float*)d_in[15];
    const float* lnf_g  = (const float*)d_in[16];
    const float* lnf_b  = (const float*)d_in[17];
    const float* lm_w   = (const float*)d_in[18];
    float* out = (float*)d_out;

    float *px, *ph, *pqkv, *patt, *pfc;
    cudaGetSymbolAddress((void**)&px,   g_x);
    cudaGetSymbolAddress((void**)&ph,   g_h);
    cudaGetSymbolAddress((void**)&pqkv, g_qkv);
    cudaGetSymbolAddress((void**)&patt, g_att);
    cudaGetSymbolAddress((void**)&pfc,  g_fc);

    const int SM_NN = (2 * 128 * 36 + 2 * 32 * 132) * 4;   // 70656 B
    const int SM_NT = (2 * 128 * 36 + 2 * 128 * 36) * 4;   // 73728 B

    cudaFuncSetAttribute(k_attn, cudaFuncAttributeMaxDynamicSharedMemorySize, ATTN_SMEM);
    cudaFuncSetAttribute(k_gemm_t<0,0>, cudaFuncAttributeMaxDynamicSharedMemorySize, SM_NN);
    cudaFuncSetAttribute(k_gemm_t<0,1>, cudaFuncAttributeMaxDynamicSharedMemorySize, SM_NN);
    cudaFuncSetAttribute(k_gemm_t<0,2>, cudaFuncAttributeMaxDynamicSharedMemorySize, SM_NN);
    cudaFuncSetAttribute(k_gemm_t<1,3>, cudaFuncAttributeMaxDynamicSharedMemorySize, SM_NT);

    k_embed<<<Nc, 256>>>(idx, wte, wpe);

    for (int l = 0; l < Lc; l++) {
        const float* g1 = ln1_g + (size_t)l * Cc;
        const float* b1 = ln1_b + (size_t)l * Cc;
        const float* wq = w_qkv + (size_t)l * Cc * C3;
        const float* bq = b_qkv + (size_t)l * C3;
        const float* wp = w_proj + (size_t)l * Cc * Cc;
        const float* bp = b_proj + (size_t)l * Cc;
        const float* g2 = ln2_g + (size_t)l * Cc;
        const float* b2 = ln2_b + (size_t)l * Cc;
        const float* wf = w_fc + (size_t)l * Cc * C4;
        const float* bf = b_fc + (size_t)l * C4;
        const float* w2 = w_fc2 + (size_t)l * C4 * Cc;
        const float* bz = b_fc2 + (size_t)l * Cc;

        k_ln<<<Nc, 256>>>(px, ph, g1, b1);
        k_gemm_t<0,0><<<dim3(C3 / 128, Nc / 128), 256, SM_NN>>>(ph, wq, bq, nullptr, pqkv, Nc, C3, Cc);
        k_attn<<<dim3(Tc / 64, Hc, Bc), 256, ATTN_SMEM>>>(pqkv);
        k_gemm_t<0,1><<<dim3(Cc / 128, Nc / 128), 256, SM_NN>>>(patt, wp, bp, px, px, Nc, Cc, Cc);
        k_ln<<<Nc, 256>>>(px, ph, g2, b2);
        k_gemm_t<0,2><<<dim3(C4 / 128, Nc / 128), 256, SM_NN>>>(ph, wf, bf, nullptr, pfc, Nc, C4, Cc);
        k_gemm_t<0,1><<<dim3(Cc / 128, Nc / 128), 256, SM_NN>>>(pfc, w2, bz, px, px, Nc, Cc, C4);
    }

    k_ln<<<Nc, 256>>>(px, ph, lnf_g, lnf_b);

    const long long NV = (long long)Nc * Vc;
    if ((long long)out_size >= NV) {
        k_gemm_t<1,3><<<dim3((Vc + 127) / 128, Nc / 128), 256, SM_NT>>>(ph, lm_w, nullptr, nullptr, out, Nc, Vc, Cc);
        k_nll<<<Nc, 256>>>(out, tgt);
        if ((long long)out_size >= NV + 1)
            k_loss_reduce<<<1, 1024>>>(out + NV);
    }
}